// round 16
// baseline (speedup 1.0000x reference)
#include <cuda_runtime.h>
#include <cuda_bf16.h>

#define N_NODES 5
#define EMB 16
#define HID 32

// ---------------------------------------------------------------------------
// Single fused PERSISTENT kernel, one wave, warp-autonomous streaming.
// Prologue (once per block): 5-node GCN -> 6x16 LUT in smem; weights staged
//   transposed+padded so every LDS is bank-conflict-free. Each warp's FIRST
//   tile of gs indices is prefetched into smem BEFORE the prologue, so its
//   load latency rides under the weight loads + GCN chain, and the first
//   stores issue immediately when the LUT lands (LDS, not a fresh L2 trip).
// Main: each warp independently walks 256-quad warp-tiles, static stride,
//   zero barriers/atomics. Lane l handles quads {base + l + u*32}: each step
//   is a fully-coalesced 512B/warp STG.128 stream via __stcs.
// ---------------------------------------------------------------------------
#define TPB 256
#define QPT 8
#define WTILE (32 * QPT)   // 256 quads per warp-tile

__global__ void __launch_bounds__(TPB, 8)
scatter_gcn(const int* __restrict__ gs,
            const float* __restrict__ emb,   // [5,16]
            const float* __restrict__ A,     // [5,5]
            const float* __restrict__ W0,    // [32,16]
            const float* __restrict__ W1,    // [32,32]
            const float* __restrict__ W2,    // [32,32]
            const float* __restrict__ Wf,    // [16,32]
            const float* __restrict__ bf,    // [16]
            float4* __restrict__ out,
            int nquads, int nwtiles)
{
    __shared__ float sE[N_NODES * EMB];
    __shared__ float sA[N_NODES * N_NODES];
    __shared__ float sW0T[EMB * 33];           // W0T[j][o]
    __shared__ float sW1T[HID * 33];           // W1T[j][o]
    __shared__ float sW2T[HID * 33];           // W2T[j][o]
    __shared__ float sWfT[HID * 17];           // WfT[j][e]
    __shared__ float sbf[EMB];
    __shared__ float x0[N_NODES][EMB];
    __shared__ float h[N_NODES][HID];
    __shared__ float y[N_NODES][HID];
    __shared__ float4 slut[6 * 4];             // final LUT: 6 rows x 4 quads
    __shared__ int sgs[TPB * QPT];             // first-tile gs indices (8KB)

    const int t = threadIdx.x;
    const int lane = t & 31;
    const int wid = t >> 5;
    const int gwarp = blockIdx.x * (TPB / 32) + wid;     // 0..9471
    const int nwarps = gridDim.x * (TPB / 32);

    // ---- prefetch this warp's FIRST tile of gs (latency hides in prologue)
    const bool first_ok = (gwarp * WTILE + lane + (QPT - 1) * 32 < nquads);
    if (first_ok) {
        const int* __restrict__ g = gs + ((gwarp * WTILE + lane) >> 2);
        #pragma unroll
        for (int u = 0; u < QPT; u++)
            sgs[wid * WTILE + u * 32 + lane] = __ldg(g + u * 8);
    }

    // ---- stage weights (conflict-free transposed STS) ----
    for (int i = t; i < N_NODES * EMB; i += TPB) sE[i] = emb[i];
    for (int i = t; i < N_NODES * N_NODES; i += TPB) sA[i] = A[i];
    for (int i = t; i < HID * EMB; i += TPB) {
        int o = i / EMB, j = i % EMB;
        sW0T[j * 33 + o] = W0[i];
    }
    for (int i = t; i < HID * HID; i += TPB) {
        int o = i / HID, j = i % HID;
        sW1T[j * 33 + o] = W1[i];
    }
    for (int i = t; i < HID * HID; i += TPB) {
        int o = i / HID, j = i % HID;
        sW2T[j * 33 + o] = W2[i];
    }
    for (int i = t; i < EMB * HID; i += TPB) {
        int e = i / HID, j = i % HID;
        sWfT[j * 17 + e] = Wf[i];
    }
    for (int i = t; i < EMB; i += TPB) sbf[i] = bf[i];
    __syncthreads();

    // ---- GCN stages (all LDS conflict-free) ----
    if (t < N_NODES * EMB) {
        int i = t / EMB, j = t % EMB;
        float s = 0.f;
        #pragma unroll
        for (int k = 0; k < N_NODES; k++) s += sA[i * N_NODES + k] * sE[k * EMB + j];
        x0[i][j] = s;
    }
    __syncthreads();

    if (t < N_NODES * HID) {
        int i = t / HID, o = t % HID;
        float s = 0.f;
        #pragma unroll
        for (int j = 0; j < EMB; j++) s += x0[i][j] * sW0T[j * 33 + o];
        h[i][o] = fmaxf(s, 0.f);
    }
    __syncthreads();

    if (t < N_NODES * HID) {
        int i = t / HID, o = t % HID;
        float s = 0.f;
        #pragma unroll
        for (int k = 0; k < N_NODES; k++) s += sA[i * N_NODES + k] * h[k][o];
        y[i][o] = s;
    }
    __syncthreads();
    if (t < N_NODES * HID) {
        int i = t / HID, o = t % HID;
        float s = 0.f;
        #pragma unroll
        for (int j = 0; j < HID; j++) s += y[i][j] * sW1T[j * 33 + o];
        h[i][o] = fmaxf(s, 0.f);
    }
    __syncthreads();

    if (t < N_NODES * HID) {
        int i = t / HID, o = t % HID;
        float s = 0.f;
        #pragma unroll
        for (int k = 0; k < N_NODES; k++) s += sA[i * N_NODES + k] * h[k][o];
        y[i][o] = s;
    }
    __syncthreads();
    if (t < N_NODES * HID) {
        int i = t / HID, o = t % HID;
        float s = 0.f;
        #pragma unroll
        for (int j = 0; j < HID; j++) s += y[i][j] * sW2T[j * 33 + o];
        h[i][o] = fmaxf(s, 0.f);
    }
    __syncthreads();

    float* slutf = reinterpret_cast<float*>(slut);
    if (t < N_NODES * EMB) {
        int i = t / EMB, e = t % EMB;
        float s = sbf[e];
        #pragma unroll
        for (int j = 0; j < HID; j++) s += h[i][j] * sWfT[j * 17 + e];
        slutf[(i + 1) * EMB + e] = s;
    }
    if (t < EMB) slutf[t] = sE[t];
    __syncthreads();   // LUT + sgs ready — last block-wide sync

    // ---- warp-autonomous streaming loop (no barriers, no atomics) ----
    const int q = lane & 3;                                 // lane-within-cell
    const float4* __restrict__ lutq = slut + q;

    int wt = gwarp;
    // first tile: indices come from smem (prefetched before the prologue)
    if (wt < nwtiles) {
        const int base = wt * WTILE + lane;
        float4* __restrict__ o = out + base;
        if (first_ok) {
            #pragma unroll
            for (int u = 0; u < QPT; u++) {
                int c = sgs[wid * WTILE + u * 32 + lane];
                __stcs(o + u * 32, lutq[c * 4]);
            }
        } else {
            #pragma unroll
            for (int u = 0; u < QPT; u++) {
                int idx = base + u * 32;
                if (idx < nquads) {
                    int cc = __ldg(gs + (idx >> 2));
                    __stcs(o + u * 32, lutq[cc * 4]);
                }
            }
        }
        wt += nwarps;
    }

    for (; wt < nwtiles; wt += nwarps) {
        const int base = wt * WTILE + lane;
        float4* __restrict__ o = out + base;

        if (base + (QPT - 1) * 32 < nquads) {
            // fast path: 8 independent gs loads, then 8 coalesced 512B stores
            const int* __restrict__ g = gs + (base >> 2);
            int c[QPT];
            #pragma unroll
            for (int u = 0; u < QPT; u++) c[u] = __ldg(g + u * 8);
            #pragma unroll
            for (int u = 0; u < QPT; u++) {
                float4 v = lutq[c[u] * 4];
                __stcs(o + u * 32, v);
            }
        } else {
            #pragma unroll
            for (int u = 0; u < QPT; u++) {
                int idx = base + u * 32;
                if (idx < nquads) {
                    int cc = __ldg(gs + (idx >> 2));
                    __stcs(o + u * 32, lutq[cc * 4]);
                }
            }
        }
    }
}

// ---------------------------------------------------------------------------
extern "C" void kernel_launch(void* const* d_in, const int* in_sizes, int n_in,
                              void* d_out, int out_size)
{
    const int*   gs  = (const int*)d_in[0];    // game_state [256,128,128]
    const float* emb = (const float*)d_in[1];  // [5,16]
    const float* A   = (const float*)d_in[2];  // [5,5]
    const float* W0  = (const float*)d_in[3];  // [32,16]
    const float* W1  = (const float*)d_in[4];  // [32,32]
    const float* W2  = (const float*)d_in[5];  // [32,32]
    const float* Wf  = (const float*)d_in[6];  // [16,32]
    const float* bf  = (const float*)d_in[7];  // [16]
    float4* out = (float4*)d_out;

    const int ncells  = in_sizes[0];           // 4,194,304
    const int nquads  = ncells * 4;            // 16,777,216 float4 stores
    const int nwtiles = (nquads + WTILE - 1) / WTILE;   // 65,536

    // one wave: 148 SMs x 8 resident 256-thread blocks (regs forced <=32)
    int blocks = 148 * 8;

    scatter_gcn<<<blocks, TPB>>>(gs, emb, A, W0, W1, W2, Wf, bf, out,
                                 nquads, nwtiles);
}